// round 8
// baseline (speedup 1.0000x reference)
#include <cuda_runtime.h>
#include <cuda_bf16.h>
#include <cstdint>

#define NN   50000
#define EE   800000
#define CIN  64
#define CH   128
#define COUT 2
#define GG   512

#define NTILES   ((NN + 127) / 128)   // 391
#define GRID_G   148

// ---------------- scratch (static device globals; no allocation) -------------
__device__ float g_hA[NN * CH];
__device__ float g_hB[NN * CH];
__device__ float g_agg[NN * CH];
__device__ uint32_t g_hbf[NN * 64];   // bf16x2-packed shadow of current h (128 ch)
__device__ uint32_t g_xbf[NN * 32];   // bf16x2-packed x (64 ch)
__device__ int   g_deg[NN];
__device__ int   g_inc[NN];
__device__ int   g_rowptr[NN + 1];
__device__ int   g_cursor[NN];
__device__ int   g_col[EE];
__device__ int   g_bsum[64];
__device__ int   g_gcnt[GG];
__device__ float g_gsum[GG * CH];
// pre-transposed, bf16-split weights, linear [N=128][K=256] per conv
__device__ __nv_bfloat16 g_Bhi[12 * 32768];
__device__ __nv_bfloat16 g_Blo[12 * 32768];

__device__ __forceinline__ uint32_t packbf2(float x, float y) {
    __nv_bfloat16 a = __float2bfloat16(x), b = __float2bfloat16(y);
    return ((uint32_t)__bfloat16_as_ushort(b) << 16) | __bfloat16_as_ushort(a);
}
__device__ __forceinline__ float2 unpackbf2(uint32_t u) {
    __nv_bfloat162 b = *(__nv_bfloat162*)&u;
    return __bfloat1622float2(b);
}

// ---------------- preprocessing (grid-parallel, 6 kernels) --------------------
__global__ void k_init_prepw(const float* __restrict__ Wl0, const float* __restrict__ Wr0,
                             const float* __restrict__ Wl, const float* __restrict__ Wr) {
    int idx = blockIdx.x * blockDim.x + threadIdx.x;
    if (idx < NN) { g_deg[idx] = 0; g_cursor[idx] = 0; }
    if (idx < GG) g_gcnt[idx] = 0;
    if (idx < GG * CH) g_gsum[idx] = 0.f;
    if (idx >= 12 * 32768) return;
    int ci = idx >> 15;
    int r  = idx & 32767;
    int j  = r >> 8;      // out col (0..127) -> B row n
    int k  = r & 255;     // concat K index
    float w = 0.f;
    if (ci == 0) {
        if (k < CIN)                  w = Wl0[k * CH + j];
        else if (k >= 128 && k < 192) w = Wr0[(k - 128) * CH + j];
    } else {
        int li = ci - 1;
        if (k < 128) w = Wl[((size_t)li * CH + k) * CH + j];
        else         w = Wr[((size_t)li * CH + (k - 128)) * CH + j];
    }
    __nv_bfloat16 hi = __float2bfloat16(w);
    __nv_bfloat16 lo = __float2bfloat16(w - __bfloat162float(hi));
    g_Bhi[idx] = hi;
    g_Blo[idx] = lo;
}

// degree count + per-graph count + x -> bf16 pack
__global__ void k_count2(const int* __restrict__ dst, const int* __restrict__ batch,
                         const float* __restrict__ x) {
    int i = blockIdx.x * blockDim.x + threadIdx.x;
    if (i < EE) atomicAdd(&g_deg[dst[i]], 1);
    if (i < NN) atomicAdd(&g_gcnt[batch[i]], 1);
    if (i < NN * 32) {
        float2 v = *(const float2*)(x + (size_t)i * 2);
        g_xbf[i] = packbf2(v.x, v.y);
    }
}

__global__ void k_scan1() {
    __shared__ int s[1024];
    int tid = threadIdx.x;
    int idx = blockIdx.x * 1024 + tid;
    int v = (idx < NN) ? g_deg[idx] : 0;
    s[tid] = v;
    __syncthreads();
    for (int off = 1; off < 1024; off <<= 1) {
        int t = (tid >= off) ? s[tid - off] : 0;
        __syncthreads();
        s[tid] += t;
        __syncthreads();
    }
    if (idx < NN) g_inc[idx] = s[tid];
    if (tid == 1023) g_bsum[blockIdx.x] = s[1023];
}

__global__ void k_scan2(int nb) {
    if (threadIdx.x == 0 && blockIdx.x == 0) {
        int run = 0;
        for (int i = 0; i < nb; i++) { int v = g_bsum[i]; g_bsum[i] = run; run += v; }
    }
}

__global__ void k_scan3() {
    int i = blockIdx.x * blockDim.x + threadIdx.x;
    if (i < NN) g_rowptr[i + 1] = g_inc[i] + g_bsum[i >> 10];
    if (i == 0) g_rowptr[0] = 0;
}

__global__ void k_fill(const int* __restrict__ src, const int* __restrict__ dst) {
    int e = blockIdx.x * blockDim.x + threadIdx.x;
    if (e < EE) {
        int d = dst[e];
        int pos = g_rowptr[d] + atomicAdd(&g_cursor[d], 1);
        g_col[pos] = src[e];
    }
}

// ---------------- neighbor mean aggregation (warp per node, bf16 gather) ------
// K=128: lane covers 4 channels (uint2 = 2 bf16x2). K=64: lane covers 2 (1 u32).
template <int K>
__global__ void __launch_bounds__(256, 8)
k_agg(const uint32_t* __restrict__ hbf, float* __restrict__ agg) {
    int node = blockIdx.x * 8 + (threadIdx.x >> 5);
    int lid = threadIdx.x & 31;
    if (node >= NN) return;
    int js = g_rowptr[node], je = g_rowptr[node + 1];
    if (K == 128) {
        float a0 = 0.f, a1 = 0.f, a2 = 0.f, a3 = 0.f;
        float b0 = 0.f, b1 = 0.f, b2 = 0.f, b3 = 0.f;
        int j = js;
        for (; j + 4 <= je; j += 4) {
            int u0 = g_col[j], u1 = g_col[j + 1], u2 = g_col[j + 2], u3 = g_col[j + 3];
            uint2 p0 = *(const uint2*)(hbf + (size_t)u0 * 64 + lid * 2);
            uint2 p1 = *(const uint2*)(hbf + (size_t)u1 * 64 + lid * 2);
            uint2 p2 = *(const uint2*)(hbf + (size_t)u2 * 64 + lid * 2);
            uint2 p3 = *(const uint2*)(hbf + (size_t)u3 * 64 + lid * 2);
            float2 v;
            v = unpackbf2(p0.x); a0 += v.x; a1 += v.y;
            v = unpackbf2(p0.y); a2 += v.x; a3 += v.y;
            v = unpackbf2(p1.x); b0 += v.x; b1 += v.y;
            v = unpackbf2(p1.y); b2 += v.x; b3 += v.y;
            v = unpackbf2(p2.x); a0 += v.x; a1 += v.y;
            v = unpackbf2(p2.y); a2 += v.x; a3 += v.y;
            v = unpackbf2(p3.x); b0 += v.x; b1 += v.y;
            v = unpackbf2(p3.y); b2 += v.x; b3 += v.y;
        }
        for (; j < je; j++) {
            uint2 p0 = *(const uint2*)(hbf + (size_t)g_col[j] * 64 + lid * 2);
            float2 v;
            v = unpackbf2(p0.x); a0 += v.x; a1 += v.y;
            v = unpackbf2(p0.y); a2 += v.x; a3 += v.y;
        }
        float inv = (je > js) ? 1.f / (float)(je - js) : 0.f;
        float4 o;
        o.x = (a0 + b0) * inv; o.y = (a1 + b1) * inv;
        o.z = (a2 + b2) * inv; o.w = (a3 + b3) * inv;
        *(float4*)(agg + (size_t)node * 128 + lid * 4) = o;
    } else {
        float a0 = 0.f, a1 = 0.f, b0 = 0.f, b1 = 0.f;
        int j = js;
        for (; j + 4 <= je; j += 4) {
            int u0 = g_col[j], u1 = g_col[j + 1], u2 = g_col[j + 2], u3 = g_col[j + 3];
            uint32_t p0 = hbf[(size_t)u0 * 32 + lid];
            uint32_t p1 = hbf[(size_t)u1 * 32 + lid];
            uint32_t p2 = hbf[(size_t)u2 * 32 + lid];
            uint32_t p3 = hbf[(size_t)u3 * 32 + lid];
            float2 v;
            v = unpackbf2(p0); a0 += v.x; a1 += v.y;
            v = unpackbf2(p1); b0 += v.x; b1 += v.y;
            v = unpackbf2(p2); a0 += v.x; a1 += v.y;
            v = unpackbf2(p3); b0 += v.x; b1 += v.y;
        }
        for (; j < je; j++) {
            float2 v = unpackbf2(hbf[(size_t)g_col[j] * 32 + lid]);
            a0 += v.x; a1 += v.y;
        }
        float inv = (je > js) ? 1.f / (float)(je - js) : 0.f;
        *(float2*)(agg + (size_t)node * 64 + lid * 2) =
            make_float2((a0 + b0) * inv, (a1 + b1) * inv);
    }
}

// ---------------- HMMA bf16 split-3 dual GEMM --------------------------------
// out[m,:] = agg @ Wl + h @ Wr + b ; activation; also writes bf16 shadow.
// ACT: 0 none, 1 relu, 2 leaky(0.01), 3 none + fused global pool (no shadow)
#define SB_STR 264
#define SA_STR 136
#define SMO_BH 0
#define SMO_BL (128 * SB_STR * 2)
#define SMO_AH (2 * 128 * SB_STR * 2)
#define SMO_AL (2 * 128 * SB_STR * 2 + 128 * SA_STR * 2)
#define SM_TOT (2 * 128 * SB_STR * 2 + 2 * 128 * SA_STR * 2)  // 204800 B

__device__ __forceinline__ void mma16816(float* d, const uint32_t* a,
                                         uint32_t b0, uint32_t b1) {
    asm volatile(
        "mma.sync.aligned.m16n8k16.row.col.f32.bf16.bf16.f32 "
        "{%0,%1,%2,%3}, {%4,%5,%6,%7}, {%8,%9}, {%0,%1,%2,%3};"
        : "+f"(d[0]), "+f"(d[1]), "+f"(d[2]), "+f"(d[3])
        : "r"(a[0]), "r"(a[1]), "r"(a[2]), "r"(a[3]), "r"(b0), "r"(b1));
}

template <int KIN, int ACT>
__global__ void __launch_bounds__(256, 1)
k_hgemm(const float* __restrict__ Xa, const float* __restrict__ Xh,
        const int* __restrict__ batch,
        const __nv_bfloat16* __restrict__ Bhi, const __nv_bfloat16* __restrict__ Blo,
        const float* __restrict__ bias, float* __restrict__ out,
        uint32_t* __restrict__ hbf) {
    extern __shared__ char sm[];
    __nv_bfloat16* sBh = (__nv_bfloat16*)(sm + SMO_BH);
    __nv_bfloat16* sBl = (__nv_bfloat16*)(sm + SMO_BL);
    __nv_bfloat16* sAh = (__nv_bfloat16*)(sm + SMO_AH);
    __nv_bfloat16* sAl = (__nv_bfloat16*)(sm + SMO_AL);

    const int tid = threadIdx.x;
    const int wid = tid >> 5, lid = tid & 31;
    const int g = lid >> 2, tig = lid & 3;
    const int m0 = (wid & 3) * 32;
    const int n0 = (wid >> 2) * 64;

    for (int i = tid; i < 4096; i += 256) {
        int n = i >> 5, kq = i & 31;
        float4 vh = ((const float4*)Bhi)[i];
        float4 vl = ((const float4*)Blo)[i];
        *(float4*)&sBh[n * SB_STR + kq * 8] = vh;
        *(float4*)&sBl[n * SB_STR + kq * 8] = vl;
    }

    const uint32_t* uBh = (const uint32_t*)sBh;
    const uint32_t* uBl = (const uint32_t*)sBl;
    const uint32_t* uAh = (const uint32_t*)sAh;
    const uint32_t* uAl = (const uint32_t*)sAl;
    constexpr int KSTEPS = (KIN == 64) ? 4 : 8;

    for (int t = blockIdx.x; t < NTILES; t += GRID_G) {
        const int row0 = t * 128;
        float acc[2][8][4];
#pragma unroll
        for (int mt = 0; mt < 2; mt++)
#pragma unroll
            for (int nt = 0; nt < 8; nt++)
#pragma unroll
                for (int q = 0; q < 4; q++) acc[mt][nt][q] = 0.f;

        for (int s = 0; s < 2; s++) {
            const float* X = s ? Xh : Xa;
            __syncthreads();
            for (int it = tid; it < 4096; it += 256) {
                int row = it >> 5, k0 = (it & 31) * 4;
                float4 v = make_float4(0.f, 0.f, 0.f, 0.f);
                int gr = row0 + row;
                if (gr < NN && k0 < KIN)
                    v = *(const float4*)(X + (size_t)gr * KIN + k0);
                float h0 = __bfloat162float(__float2bfloat16(v.x));
                float h1 = __bfloat162float(__float2bfloat16(v.y));
                float h2 = __bfloat162float(__float2bfloat16(v.z));
                float h3 = __bfloat162float(__float2bfloat16(v.w));
                *(uint2*)&sAh[row * SA_STR + k0] =
                    make_uint2(packbf2(v.x, v.y), packbf2(v.z, v.w));
                *(uint2*)&sAl[row * SA_STR + k0] =
                    make_uint2(packbf2(v.x - h0, v.y - h1), packbf2(v.z - h2, v.w - h3));
            }
            __syncthreads();

#pragma unroll
            for (int ks = 0; ks < KSTEPS; ks++) {
                const int k0 = ks * 16;
                uint32_t ah[2][4], al[2][4];
#pragma unroll
                for (int mt = 0; mt < 2; mt++) {
                    int r = m0 + mt * 16 + g;
                    int ai = r * (SA_STR / 2) + (k0 >> 1) + tig;
                    ah[mt][0] = uAh[ai];
                    ah[mt][1] = uAh[ai + 8 * (SA_STR / 2)];
                    ah[mt][2] = uAh[ai + 4];
                    ah[mt][3] = uAh[ai + 8 * (SA_STR / 2) + 4];
                    al[mt][0] = uAl[ai];
                    al[mt][1] = uAl[ai + 8 * (SA_STR / 2)];
                    al[mt][2] = uAl[ai + 4];
                    al[mt][3] = uAl[ai + 8 * (SA_STR / 2) + 4];
                }
                const int kg = s * 128 + k0;
#pragma unroll
                for (int nt = 0; nt < 8; nt++) {
                    int c = n0 + nt * 8 + g;
                    int bi = c * (SB_STR / 2) + (kg >> 1) + tig;
                    uint32_t bh0 = uBh[bi], bh1 = uBh[bi + 4];
                    uint32_t bl0 = uBl[bi], bl1 = uBl[bi + 4];
#pragma unroll
                    for (int mt = 0; mt < 2; mt++) {
                        mma16816(acc[mt][nt], ah[mt], bh0, bh1);
                        mma16816(acc[mt][nt], ah[mt], bl0, bl1);
                        mma16816(acc[mt][nt], al[mt], bh0, bh1);
                    }
                }
            }
        }

        // epilogue: bias + activation + store fp32 (+ bf16 shadow | fused pool)
#pragma unroll
        for (int mt = 0; mt < 2; mt++) {
#pragma unroll
            for (int half = 0; half < 2; half++) {
                int gr = row0 + m0 + mt * 16 + g + half * 8;
                if (gr < NN) {
                    int bidx = (ACT == 3) ? __ldg(batch + gr) : 0;
#pragma unroll
                    for (int nt = 0; nt < 8; nt++) {
                        int c = n0 + nt * 8 + tig * 2;
                        float v0 = acc[mt][nt][half * 2 + 0] + __ldg(bias + c);
                        float v1 = acc[mt][nt][half * 2 + 1] + __ldg(bias + c + 1);
                        if (ACT == 1) {
                            v0 = fmaxf(v0, 0.f); v1 = fmaxf(v1, 0.f);
                        } else if (ACT == 2) {
                            v0 = (v0 > 0.f) ? v0 : 0.01f * v0;
                            v1 = (v1 > 0.f) ? v1 : 0.01f * v1;
                        }
                        if (ACT == 3) {
                            atomicAdd(&g_gsum[bidx * CH + c], v0);
                            atomicAdd(&g_gsum[bidx * CH + c + 1], v1);
                        } else {
                            *(float2*)(out + (size_t)gr * CH + c) = make_float2(v0, v1);
                            hbf[(size_t)gr * 64 + (c >> 1)] = packbf2(v0, v1);
                        }
                    }
                }
            }
        }
    }
}

// ---------------- head --------------------------------------------------------
__global__ void k_head(const float* __restrict__ headW,
                       const float* __restrict__ headb,
                       float* __restrict__ out) {
    int tid = blockIdx.x * blockDim.x + threadIdx.x;
    if (tid >= GG * COUT) return;
    int g = tid >> 1;
    int o = tid & 1;
    float cnt = (float)g_gcnt[g];
    float inv = 1.f / fmaxf(cnt, 1.f);
    float acc = headb[o];
#pragma unroll 8
    for (int k = 0; k < CH; k++)
        acc += g_gsum[g * CH + k] * inv * headW[k * COUT + o];
    out[tid] = acc;
}

// ---------------- host driver -------------------------------------------------
extern "C" void kernel_launch(void* const* d_in, const int* in_sizes, int n_in,
                              void* d_out, int out_size) {
    const float* x     = (const float*)d_in[0];
    const int*   ei    = (const int*)d_in[1];
    const int*   srcp  = ei;
    const int*   dstp  = ei + EE;
    const int*   batch = (const int*)d_in[2];
    const float* Wl0   = (const float*)d_in[3];
    const float* Wr0   = (const float*)d_in[4];
    const float* b0    = (const float*)d_in[5];
    const float* Wl    = (const float*)d_in[6];
    const float* Wr    = (const float*)d_in[7];
    const float* bb    = (const float*)d_in[8];
    const float* headW = (const float*)d_in[9];
    const float* headb = (const float*)d_in[10];
    float* out = (float*)d_out;

    float *hA, *hB, *agg;
    uint32_t *hbf, *xbf;
    __nv_bfloat16 *Bhi, *Blo;
    cudaGetSymbolAddress((void**)&hA, g_hA);
    cudaGetSymbolAddress((void**)&hB, g_hB);
    cudaGetSymbolAddress((void**)&agg, g_agg);
    cudaGetSymbolAddress((void**)&hbf, g_hbf);
    cudaGetSymbolAddress((void**)&xbf, g_xbf);
    cudaGetSymbolAddress((void**)&Bhi, g_Bhi);
    cudaGetSymbolAddress((void**)&Blo, g_Blo);

    cudaFuncSetAttribute(k_hgemm<64, 1>,  cudaFuncAttributeMaxDynamicSharedMemorySize, SM_TOT);
    cudaFuncSetAttribute(k_hgemm<128, 1>, cudaFuncAttributeMaxDynamicSharedMemorySize, SM_TOT);
    cudaFuncSetAttribute(k_hgemm<128, 2>, cudaFuncAttributeMaxDynamicSharedMemorySize, SM_TOT);
    cudaFuncSetAttribute(k_hgemm<128, 3>, cudaFuncAttributeMaxDynamicSharedMemorySize, SM_TOT);

    // --- preprocessing: grid-parallel, 6 launches ---
    k_init_prepw<<<(12 * 32768 + 255) / 256, 256>>>(Wl0, Wr0, Wl, Wr);
    k_count2<<<(NN * 32 + 255) / 256, 256>>>(dstp, batch, x);
    k_scan1<<<(NN + 1023) / 1024, 1024>>>();
    k_scan2<<<1, 32>>>((NN + 1023) / 1024);
    k_scan3<<<(NN + 255) / 256, 256>>>();
    k_fill<<<(EE + 255) / 256, 256>>>(srcp, dstp);

    // --- conv 0: C_IN=64 -> 128, ReLU (gather from bf16 x) ---
    k_agg<64><<<(NN + 7) / 8, 256>>>(xbf, agg);
    k_hgemm<64, 1><<<GRID_G, 256, SM_TOT>>>(agg, x, batch, Bhi, Blo, b0, hA, hbf);

    // --- convs 1..11 (conv 11 fuses global mean pool) ---
    const int act[11] = {1, 1, 2, 1, 1, 1, 2, 1, 1, 1, 3};
    const float* cur = hA;
    float* nxt = hB;
    for (int li = 0; li < 11; li++) {
        k_agg<128><<<(NN + 7) / 8, 256>>>(hbf, agg);
        const __nv_bfloat16* bh = Bhi + (size_t)(li + 1) * 32768;
        const __nv_bfloat16* bl = Blo + (size_t)(li + 1) * 32768;
        const float* bi = bb + (size_t)li * CH;
        if (act[li] == 1)
            k_hgemm<128, 1><<<GRID_G, 256, SM_TOT>>>(agg, cur, batch, bh, bl, bi, nxt, hbf);
        else if (act[li] == 2)
            k_hgemm<128, 2><<<GRID_G, 256, SM_TOT>>>(agg, cur, batch, bh, bl, bi, nxt, hbf);
        else
            k_hgemm<128, 3><<<GRID_G, 256, SM_TOT>>>(agg, cur, batch, bh, bl, bi, nxt, hbf);
        const float* t = cur;
        cur = nxt;
        nxt = (float*)t;
    }

    // --- head ---
    k_head<<<(GG * COUT + 255) / 256, 256>>>(headW, headb, out);
}

// round 9
// speedup vs baseline: 1.0991x; 1.0991x over previous
#include <cuda_runtime.h>
#include <cuda_bf16.h>
#include <cstdint>

#define NN   50000
#define EE   800000
#define CIN  64
#define CH   128
#define COUT 2
#define GG   512

#define NTILES   ((NN + 127) / 128)   // 391
#define GRID_G   148

// ---------------- scratch (static device globals; no allocation) -------------
__device__ float g_hA[NN * CH];
__device__ float g_hB[NN * CH];
__device__ float g_agg[NN * CH];
__device__ int   g_deg[NN];
__device__ int   g_inc[NN];
__device__ int   g_rowptr[NN + 1];
__device__ int   g_cursor[NN];
__device__ int   g_col[EE];
__device__ int   g_bsum[64];
__device__ int   g_gcnt[GG];
__device__ float g_gsum[GG * CH];
// pre-transposed, bf16-split weights, linear [N=128][K=256] per conv
__device__ __nv_bfloat16 g_Bhi[12 * 32768];
__device__ __nv_bfloat16 g_Blo[12 * 32768];

__device__ __forceinline__ uint32_t packbf2(float x, float y) {
    __nv_bfloat16 a = __float2bfloat16(x), b = __float2bfloat16(y);
    return ((uint32_t)__bfloat16_as_ushort(b) << 16) | __bfloat16_as_ushort(a);
}

// ---------------- preprocessing (grid-parallel, 6 kernels) --------------------
__global__ void k_init_prepw(const float* __restrict__ Wl0, const float* __restrict__ Wr0,
                             const float* __restrict__ Wl, const float* __restrict__ Wr) {
    int idx = blockIdx.x * blockDim.x + threadIdx.x;
    if (idx < NN) { g_deg[idx] = 0; g_cursor[idx] = 0; }
    if (idx < GG) g_gcnt[idx] = 0;
    if (idx < GG * CH) g_gsum[idx] = 0.f;
    if (idx >= 12 * 32768) return;
    int ci = idx >> 15;
    int r  = idx & 32767;
    int j  = r >> 8;      // out col (0..127) -> B row n
    int k  = r & 255;     // concat K index
    float w = 0.f;
    if (ci == 0) {
        if (k < CIN)                  w = Wl0[k * CH + j];
        else if (k >= 128 && k < 192) w = Wr0[(k - 128) * CH + j];
    } else {
        int li = ci - 1;
        if (k < 128) w = Wl[((size_t)li * CH + k) * CH + j];
        else         w = Wr[((size_t)li * CH + (k - 128)) * CH + j];
    }
    __nv_bfloat16 hi = __float2bfloat16(w);
    __nv_bfloat16 lo = __float2bfloat16(w - __bfloat162float(hi));
    g_Bhi[idx] = hi;
    g_Blo[idx] = lo;
}

__global__ void k_count2(const int* __restrict__ dst, const int* __restrict__ batch) {
    int i = blockIdx.x * blockDim.x + threadIdx.x;
    if (i < EE) atomicAdd(&g_deg[dst[i]], 1);
    if (i < NN) atomicAdd(&g_gcnt[batch[i]], 1);
}

__global__ void k_scan1() {
    __shared__ int s[1024];
    int tid = threadIdx.x;
    int idx = blockIdx.x * 1024 + tid;
    int v = (idx < NN) ? g_deg[idx] : 0;
    s[tid] = v;
    __syncthreads();
    for (int off = 1; off < 1024; off <<= 1) {
        int t = (tid >= off) ? s[tid - off] : 0;
        __syncthreads();
        s[tid] += t;
        __syncthreads();
    }
    if (idx < NN) g_inc[idx] = s[tid];
    if (tid == 1023) g_bsum[blockIdx.x] = s[1023];
}

__global__ void k_scan2(int nb) {
    if (threadIdx.x == 0 && blockIdx.x == 0) {
        int run = 0;
        for (int i = 0; i < nb; i++) { int v = g_bsum[i]; g_bsum[i] = run; run += v; }
    }
}

__global__ void k_scan3() {
    int i = blockIdx.x * blockDim.x + threadIdx.x;
    if (i < NN) g_rowptr[i + 1] = g_inc[i] + g_bsum[i >> 10];
    if (i == 0) g_rowptr[0] = 0;
}

__global__ void k_fill(const int* __restrict__ src, const int* __restrict__ dst) {
    int e = blockIdx.x * blockDim.x + threadIdx.x;
    if (e < EE) {
        int d = dst[e];
        int pos = g_rowptr[d] + atomicAdd(&g_cursor[d], 1);
        g_col[pos] = src[e];
    }
}

// ---------------- neighbor mean aggregation (warp per node) -------------------
template <int K>
__global__ void __launch_bounds__(256, 8)
k_agg(const float* __restrict__ h, float* __restrict__ agg) {
    int node = blockIdx.x * 8 + (threadIdx.x >> 5);
    int lid = threadIdx.x & 31;
    if (node >= NN) return;
    int js = g_rowptr[node], je = g_rowptr[node + 1];
    if (K == 128) {
        const int c = lid * 4;
        float a0 = 0.f, a1 = 0.f, a2 = 0.f, a3 = 0.f;
        float b0 = 0.f, b1 = 0.f, b2 = 0.f, b3 = 0.f;
        int j = js;
        for (; j + 4 <= je; j += 4) {
            int u0 = g_col[j], u1 = g_col[j + 1], u2 = g_col[j + 2], u3 = g_col[j + 3];
            float4 v0 = *(const float4*)(h + (size_t)u0 * 128 + c);
            float4 v1 = *(const float4*)(h + (size_t)u1 * 128 + c);
            float4 v2 = *(const float4*)(h + (size_t)u2 * 128 + c);
            float4 v3 = *(const float4*)(h + (size_t)u3 * 128 + c);
            a0 += v0.x; a1 += v0.y; a2 += v0.z; a3 += v0.w;
            b0 += v1.x; b1 += v1.y; b2 += v1.z; b3 += v1.w;
            a0 += v2.x; a1 += v2.y; a2 += v2.z; a3 += v2.w;
            b0 += v3.x; b1 += v3.y; b2 += v3.z; b3 += v3.w;
        }
        for (; j < je; j++) {
            float4 v0 = *(const float4*)(h + (size_t)g_col[j] * 128 + c);
            a0 += v0.x; a1 += v0.y; a2 += v0.z; a3 += v0.w;
        }
        float inv = (je > js) ? 1.f / (float)(je - js) : 0.f;
        float4 o;
        o.x = (a0 + b0) * inv; o.y = (a1 + b1) * inv;
        o.z = (a2 + b2) * inv; o.w = (a3 + b3) * inv;
        *(float4*)(agg + (size_t)node * 128 + c) = o;
    } else {
        const int c = lid * 2;
        float a0 = 0.f, a1 = 0.f, b0 = 0.f, b1 = 0.f;
        int j = js;
        for (; j + 4 <= je; j += 4) {
            int u0 = g_col[j], u1 = g_col[j + 1], u2 = g_col[j + 2], u3 = g_col[j + 3];
            float2 v0 = *(const float2*)(h + (size_t)u0 * 64 + c);
            float2 v1 = *(const float2*)(h + (size_t)u1 * 64 + c);
            float2 v2 = *(const float2*)(h + (size_t)u2 * 64 + c);
            float2 v3 = *(const float2*)(h + (size_t)u3 * 64 + c);
            a0 += v0.x; a1 += v0.y;
            b0 += v1.x; b1 += v1.y;
            a0 += v2.x; a1 += v2.y;
            b0 += v3.x; b1 += v3.y;
        }
        for (; j < je; j++) {
            float2 v0 = *(const float2*)(h + (size_t)g_col[j] * 64 + c);
            a0 += v0.x; a1 += v0.y;
        }
        float inv = (je > js) ? 1.f / (float)(je - js) : 0.f;
        *(float2*)(agg + (size_t)node * 64 + c) =
            make_float2((a0 + b0) * inv, (a1 + b1) * inv);
    }
}

// ---------------- HMMA bf16 split-3 dual GEMM (software-pipelined) ------------
// out[m,:] = agg @ Wl + h @ Wr + b ; activation.
// ACT: 0 none, 1 relu, 2 leaky(0.01), 3 none + fused global pool
#define SB_STR 264
#define SA_STR 136
#define SMO_BH 0
#define SMO_BL (128 * SB_STR * 2)
#define SMO_AH (2 * 128 * SB_STR * 2)
#define SMO_AL (2 * 128 * SB_STR * 2 + 128 * SA_STR * 2)
#define SM_TOT (2 * 128 * SB_STR * 2 + 2 * 128 * SA_STR * 2)  // 204800 B

__device__ __forceinline__ void mma16816(float* d, const uint32_t* a,
                                         uint32_t b0, uint32_t b1) {
    asm volatile(
        "mma.sync.aligned.m16n8k16.row.col.f32.bf16.bf16.f32 "
        "{%0,%1,%2,%3}, {%4,%5,%6,%7}, {%8,%9}, {%0,%1,%2,%3};"
        : "+f"(d[0]), "+f"(d[1]), "+f"(d[2]), "+f"(d[3])
        : "r"(a[0]), "r"(a[1]), "r"(a[2]), "r"(a[3]), "r"(b0), "r"(b1));
}

// prefetch one A-stage (128 rows x up-to-128 cols) into registers
template <int KIN>
__device__ __forceinline__ void ld_stage(float4* R, const float* __restrict__ X,
                                         int row0, int tid) {
#pragma unroll
    for (int i = 0; i < 16; i++) {
        int it = tid + 256 * i;
        int row = it >> 5, k0 = (it & 31) * 4;
        float4 v = make_float4(0.f, 0.f, 0.f, 0.f);
        int gr = row0 + row;
        if (gr < NN && k0 < KIN)
            v = *(const float4*)(X + (size_t)gr * KIN + k0);
        R[i] = v;
    }
}

// convert + store prefetched stage into split smem
__device__ __forceinline__ void st_stage(const float4* R, __nv_bfloat16* sAh,
                                         __nv_bfloat16* sAl, int tid) {
#pragma unroll
    for (int i = 0; i < 16; i++) {
        int it = tid + 256 * i;
        int row = it >> 5, k0 = (it & 31) * 4;
        float4 v = R[i];
        float h0 = __bfloat162float(__float2bfloat16(v.x));
        float h1 = __bfloat162float(__float2bfloat16(v.y));
        float h2 = __bfloat162float(__float2bfloat16(v.z));
        float h3 = __bfloat162float(__float2bfloat16(v.w));
        *(uint2*)&sAh[row * SA_STR + k0] =
            make_uint2(packbf2(v.x, v.y), packbf2(v.z, v.w));
        *(uint2*)&sAl[row * SA_STR + k0] =
            make_uint2(packbf2(v.x - h0, v.y - h1), packbf2(v.z - h2, v.w - h3));
    }
}

template <int KSTEPS>
__device__ __forceinline__ void run_mma(float acc[2][8][4],
        const uint32_t* uAh, const uint32_t* uAl,
        const uint32_t* uBh, const uint32_t* uBl,
        int m0, int n0, int g, int tig, int kgbase) {
#pragma unroll
    for (int ks = 0; ks < KSTEPS; ks++) {
        const int k0 = ks * 16;
        uint32_t ah[2][4], al[2][4];
#pragma unroll
        for (int mt = 0; mt < 2; mt++) {
            int r = m0 + mt * 16 + g;
            int ai = r * (SA_STR / 2) + (k0 >> 1) + tig;
            ah[mt][0] = uAh[ai];
            ah[mt][1] = uAh[ai + 8 * (SA_STR / 2)];
            ah[mt][2] = uAh[ai + 4];
            ah[mt][3] = uAh[ai + 8 * (SA_STR / 2) + 4];
            al[mt][0] = uAl[ai];
            al[mt][1] = uAl[ai + 8 * (SA_STR / 2)];
            al[mt][2] = uAl[ai + 4];
            al[mt][3] = uAl[ai + 8 * (SA_STR / 2) + 4];
        }
        const int kg = kgbase + k0;
#pragma unroll
        for (int nt = 0; nt < 8; nt++) {
            int c = n0 + nt * 8 + g;
            int bi = c * (SB_STR / 2) + (kg >> 1) + tig;
            uint32_t bh0 = uBh[bi], bh1 = uBh[bi + 4];
            uint32_t bl0 = uBl[bi], bl1 = uBl[bi + 4];
#pragma unroll
            for (int mt = 0; mt < 2; mt++) {
                mma16816(acc[mt][nt], ah[mt], bh0, bh1);
                mma16816(acc[mt][nt], ah[mt], bl0, bl1);
                mma16816(acc[mt][nt], al[mt], bh0, bh1);
            }
        }
    }
}

template <int KIN, int ACT>
__global__ void __launch_bounds__(256)
k_hgemm(const float* __restrict__ Xa, const float* __restrict__ Xh,
        const int* __restrict__ batch,
        const __nv_bfloat16* __restrict__ Bhi, const __nv_bfloat16* __restrict__ Blo,
        const float* __restrict__ bias, float* __restrict__ out) {
    extern __shared__ char sm[];
    __nv_bfloat16* sBh = (__nv_bfloat16*)(sm + SMO_BH);
    __nv_bfloat16* sBl = (__nv_bfloat16*)(sm + SMO_BL);
    __nv_bfloat16* sAh = (__nv_bfloat16*)(sm + SMO_AH);
    __nv_bfloat16* sAl = (__nv_bfloat16*)(sm + SMO_AL);

    const int tid = threadIdx.x;
    const int wid = tid >> 5, lid = tid & 31;
    const int g = lid >> 2, tig = lid & 3;
    const int m0 = (wid & 3) * 32;
    const int n0 = (wid >> 2) * 64;

    for (int i = tid; i < 4096; i += 256) {
        int n = i >> 5, kq = i & 31;
        float4 vh = ((const float4*)Bhi)[i];
        float4 vl = ((const float4*)Blo)[i];
        *(float4*)&sBh[n * SB_STR + kq * 8] = vh;
        *(float4*)&sBl[n * SB_STR + kq * 8] = vl;
    }

    const uint32_t* uBh = (const uint32_t*)sBh;
    const uint32_t* uBl = (const uint32_t*)sBl;
    const uint32_t* uAh = (const uint32_t*)sAh;
    const uint32_t* uAl = (const uint32_t*)sAl;
    constexpr int KSTEPS = (KIN == 64) ? 4 : 8;

    float4 R[16];
    ld_stage<KIN>(R, Xa, blockIdx.x * 128, tid);   // prefetch first tile, stage 0

    for (int t = blockIdx.x; t < NTILES; t += GRID_G) {
        const int row0 = t * 128;
        float acc[2][8][4];
#pragma unroll
        for (int mt = 0; mt < 2; mt++)
#pragma unroll
            for (int nt = 0; nt < 8; nt++)
#pragma unroll
                for (int q = 0; q < 4; q++) acc[mt][nt][q] = 0.f;

        // ---- stage 0 (agg term) ----
        __syncthreads();                    // prior MMA/frag reads done
        st_stage(R, sAh, sAl, tid);
        __syncthreads();
        ld_stage<KIN>(R, Xh, row0, tid);    // prefetch stage 1 (hidden by MMA)
        run_mma<KSTEPS>(acc, uAh, uAl, uBh, uBl, m0, n0, g, tig, 0);

        // ---- stage 1 (self term) ----
        __syncthreads();
        st_stage(R, sAh, sAl, tid);
        __syncthreads();
        if (t + GRID_G < NTILES)
            ld_stage<KIN>(R, Xa, (t + GRID_G) * 128, tid);  // prefetch next tile s0
        run_mma<KSTEPS>(acc, uAh, uAl, uBh, uBl, m0, n0, g, tig, 128);

        // ---- epilogue: bias + activation + store (or fused pool) ----
#pragma unroll
        for (int mt = 0; mt < 2; mt++) {
#pragma unroll
            for (int half = 0; half < 2; half++) {
                int gr = row0 + m0 + mt * 16 + g + half * 8;
                if (gr < NN) {
                    int bidx = (ACT == 3) ? __ldg(batch + gr) : 0;
#pragma unroll
                    for (int nt = 0; nt < 8; nt++) {
                        int c = n0 + nt * 8 + tig * 2;
                        float v0 = acc[mt][nt][half * 2 + 0] + __ldg(bias + c);
                        float v1 = acc[mt][nt][half * 2 + 1] + __ldg(bias + c + 1);
                        if (ACT == 1) {
                            v0 = fmaxf(v0, 0.f); v1 = fmaxf(v1, 0.f);
                        } else if (ACT == 2) {
                            v0 = (v0 > 0.f) ? v0 : 0.01f * v0;
                            v1 = (v1 > 0.f) ? v1 : 0.01f * v1;
                        }
                        if (ACT == 3) {
                            atomicAdd(&g_gsum[bidx * CH + c], v0);
                            atomicAdd(&g_gsum[bidx * CH + c + 1], v1);
                        } else {
                            *(float2*)(out + (size_t)gr * CH + c) = make_float2(v0, v1);
                        }
                    }
                }
            }
        }
    }
}

// ---------------- head --------------------------------------------------------
__global__ void k_head(const float* __restrict__ headW,
                       const float* __restrict__ headb,
                       float* __restrict__ out) {
    int tid = blockIdx.x * blockDim.x + threadIdx.x;
    if (tid >= GG * COUT) return;
    int g = tid >> 1;
    int o = tid & 1;
    float cnt = (float)g_gcnt[g];
    float inv = 1.f / fmaxf(cnt, 1.f);
    float acc = headb[o];
#pragma unroll 8
    for (int k = 0; k < CH; k++)
        acc += g_gsum[g * CH + k] * inv * headW[k * COUT + o];
    out[tid] = acc;
}

// ---------------- host driver -------------------------------------------------
extern "C" void kernel_launch(void* const* d_in, const int* in_sizes, int n_in,
                              void* d_out, int out_size) {
    const float* x     = (const float*)d_in[0];
    const int*   ei    = (const int*)d_in[1];
    const int*   srcp  = ei;
    const int*   dstp  = ei + EE;
    const int*   batch = (const int*)d_in[2];
    const float* Wl0   = (const float*)d_in[3];
    const float* Wr0   = (const float*)d_in[4];
    const float* b0    = (const float*)d_in[5];
    const float* Wl    = (const float*)d_in[6];
    const float* Wr    = (const float*)d_in[7];
    const float* bb    = (const float*)d_in[8];
    const float* headW = (const float*)d_in[9];
    const float* headb = (const float*)d_in[10];
    float* out = (float*)d_out;

    float *hA, *hB, *agg;
    __nv_bfloat16 *Bhi, *Blo;
    cudaGetSymbolAddress((void**)&hA, g_hA);
    cudaGetSymbolAddress((void**)&hB, g_hB);
    cudaGetSymbolAddress((void**)&agg, g_agg);
    cudaGetSymbolAddress((void**)&Bhi, g_Bhi);
    cudaGetSymbolAddress((void**)&Blo, g_Blo);

    cudaFuncSetAttribute(k_hgemm<64, 1>,  cudaFuncAttributeMaxDynamicSharedMemorySize, SM_TOT);
    cudaFuncSetAttribute(k_hgemm<128, 1>, cudaFuncAttributeMaxDynamicSharedMemorySize, SM_TOT);
    cudaFuncSetAttribute(k_hgemm<128, 2>, cudaFuncAttributeMaxDynamicSharedMemorySize, SM_TOT);
    cudaFuncSetAttribute(k_hgemm<128, 3>, cudaFuncAttributeMaxDynamicSharedMemorySize, SM_TOT);

    // --- preprocessing: grid-parallel, 6 launches ---
    k_init_prepw<<<(12 * 32768 + 255) / 256, 256>>>(Wl0, Wr0, Wl, Wr);
    k_count2<<<(EE + 255) / 256, 256>>>(dstp, batch);
    k_scan1<<<(NN + 1023) / 1024, 1024>>>();
    k_scan2<<<1, 32>>>((NN + 1023) / 1024);
    k_scan3<<<(NN + 255) / 256, 256>>>();
    k_fill<<<(EE + 255) / 256, 256>>>(srcp, dstp);

    // --- conv 0: C_IN=64 -> 128, ReLU ---
    k_agg<64><<<(NN + 7) / 8, 256>>>(x, agg);
    k_hgemm<64, 1><<<GRID_G, 256, SM_TOT>>>(agg, x, batch, Bhi, Blo, b0, hA);

    // --- convs 1..11 (conv 11 fuses global mean pool) ---
    const int act[11] = {1, 1, 2, 1, 1, 1, 2, 1, 1, 1, 3};
    const float* cur = hA;
    float* nxt = hB;
    for (int li = 0; li < 11; li++) {
        k_agg<128><<<(NN + 7) / 8, 256>>>(cur, agg);
        const __nv_bfloat16* bh = Bhi + (size_t)(li + 1) * 32768;
        const __nv_bfloat16* bl = Blo + (size_t)(li + 1) * 32768;
        const float* bi = bb + (size_t)li * CH;
        if (act[li] == 1)
            k_hgemm<128, 1><<<GRID_G, 256, SM_TOT>>>(agg, cur, batch, bh, bl, bi, nxt);
        else if (act[li] == 2)
            k_hgemm<128, 2><<<GRID_G, 256, SM_TOT>>>(agg, cur, batch, bh, bl, bi, nxt);
        else
            k_hgemm<128, 3><<<GRID_G, 256, SM_TOT>>>(agg, cur, batch, bh, bl, bi, nxt);
        const float* t = cur;
        cur = nxt;
        nxt = (float*)t;
    }

    // --- head ---
    k_head<<<(GG * COUT + 255) / 256, 256>>>(headW, headb, out);
}

// round 12
// speedup vs baseline: 1.1239x; 1.0225x over previous
#include <cuda_runtime.h>
#include <cuda_bf16.h>
#include <cstdint>

#define NN   50000
#define EE   800000
#define CIN  64
#define CH   128
#define COUT 2
#define GG   512

#define NTILES   ((NN + 127) / 128)   // 391
#define GRID_G   148

// ---------------- scratch (static device globals; no allocation) -------------
__device__ float g_hA[NN * CH];
__device__ float g_hB[NN * CH];
__device__ float g_agg[NN * CH];
__device__ int   g_deg[NN];
__device__ int   g_inc[NN];
__device__ int   g_rowptr[NN + 1];
__device__ int   g_cursor[NN];
__device__ int   g_col[EE];
__device__ int   g_bsum[64];
__device__ int   g_gcnt[GG];
__device__ float g_gsum[GG * CH];
// pre-transposed, bf16-split weights, linear [N=128][K=256] per conv
__device__ __nv_bfloat16 g_Bhi[12 * 32768];
__device__ __nv_bfloat16 g_Blo[12 * 32768];

__device__ __forceinline__ uint32_t packbf2(float x, float y) {
    __nv_bfloat16 a = __float2bfloat16(x), b = __float2bfloat16(y);
    return ((uint32_t)__bfloat16_as_ushort(b) << 16) | __bfloat16_as_ushort(a);
}

// ---------------- preprocessing (grid-parallel, 6 kernels) --------------------
__global__ void k_init_prepw(const float* __restrict__ Wl0, const float* __restrict__ Wr0,
                             const float* __restrict__ Wl, const float* __restrict__ Wr) {
    int idx = blockIdx.x * blockDim.x + threadIdx.x;
    if (idx < NN) { g_deg[idx] = 0; g_cursor[idx] = 0; }
    if (idx < GG) g_gcnt[idx] = 0;
    if (idx < GG * CH) g_gsum[idx] = 0.f;
    if (idx >= 12 * 32768) return;
    int ci = idx >> 15;
    int r  = idx & 32767;
    int j  = r >> 8;      // out col (0..127) -> B row n
    int k  = r & 255;     // concat K index
    float w = 0.f;
    if (ci == 0) {
        if (k < CIN)                  w = Wl0[k * CH + j];
        else if (k >= 128 && k < 192) w = Wr0[(k - 128) * CH + j];
    } else {
        int li = ci - 1;
        if (k < 128) w = Wl[((size_t)li * CH + k) * CH + j];
        else         w = Wr[((size_t)li * CH + (k - 128)) * CH + j];
    }
    __nv_bfloat16 hi = __float2bfloat16(w);
    __nv_bfloat16 lo = __float2bfloat16(w - __bfloat162float(hi));
    g_Bhi[idx] = hi;
    g_Blo[idx] = lo;
}

__global__ void k_count2(const int* __restrict__ dst, const int* __restrict__ batch) {
    int i = blockIdx.x * blockDim.x + threadIdx.x;
    if (i < EE) atomicAdd(&g_deg[dst[i]], 1);
    if (i < NN) atomicAdd(&g_gcnt[batch[i]], 1);
}

__global__ void k_scan1() {
    __shared__ int s[1024];
    int tid = threadIdx.x;
    int idx = blockIdx.x * 1024 + tid;
    int v = (idx < NN) ? g_deg[idx] : 0;
    s[tid] = v;
    __syncthreads();
    for (int off = 1; off < 1024; off <<= 1) {
        int t = (tid >= off) ? s[tid - off] : 0;
        __syncthreads();
        s[tid] += t;
        __syncthreads();
    }
    if (idx < NN) g_inc[idx] = s[tid];
    if (tid == 1023) g_bsum[blockIdx.x] = s[1023];
}

__global__ void k_scan2(int nb) {
    if (threadIdx.x == 0 && blockIdx.x == 0) {
        int run = 0;
        for (int i = 0; i < nb; i++) { int v = g_bsum[i]; g_bsum[i] = run; run += v; }
    }
}

__global__ void k_scan3() {
    int i = blockIdx.x * blockDim.x + threadIdx.x;
    if (i < NN) g_rowptr[i + 1] = g_inc[i] + g_bsum[i >> 10];
    if (i == 0) g_rowptr[0] = 0;
}

__global__ void k_fill(const int* __restrict__ src, const int* __restrict__ dst) {
    int e = blockIdx.x * blockDim.x + threadIdx.x;
    if (e < EE) {
        int d = dst[e];
        int pos = g_rowptr[d] + atomicAdd(&g_cursor[d], 1);
        g_col[pos] = src[e];
    }
}

// ---------------- neighbor mean aggregation (warp per node) -------------------
template <int K>
__global__ void __launch_bounds__(256, 8)
k_agg(const float* __restrict__ h, float* __restrict__ agg) {
    int node = blockIdx.x * 8 + (threadIdx.x >> 5);
    int lid = threadIdx.x & 31;
    if (node >= NN) return;
    int js = g_rowptr[node], je = g_rowptr[node + 1];
    if (K == 128) {
        const int c = lid * 4;
        float a0 = 0.f, a1 = 0.f, a2 = 0.f, a3 = 0.f;
        float b0 = 0.f, b1 = 0.f, b2 = 0.f, b3 = 0.f;
        int j = js;
        for (; j + 4 <= je; j += 4) {
            int u0 = g_col[j], u1 = g_col[j + 1], u2 = g_col[j + 2], u3 = g_col[j + 3];
            float4 v0 = *(const float4*)(h + (size_t)u0 * 128 + c);
            float4 v1 = *(const float4*)(h + (size_t)u1 * 128 + c);
            float4 v2 = *(const float4*)(h + (size_t)u2 * 128 + c);
            float4 v3 = *(const float4*)(h + (size_t)u3 * 128 + c);
            a0 += v0.x; a1 += v0.y; a2 += v0.z; a3 += v0.w;
            b0 += v1.x; b1 += v1.y; b2 += v1.z; b3 += v1.w;
            a0 += v2.x; a1 += v2.y; a2 += v2.z; a3 += v2.w;
            b0 += v3.x; b1 += v3.y; b2 += v3.z; b3 += v3.w;
        }
        for (; j < je; j++) {
            float4 v0 = *(const float4*)(h + (size_t)g_col[j] * 128 + c);
            a0 += v0.x; a1 += v0.y; a2 += v0.z; a3 += v0.w;
        }
        float inv = (je > js) ? 1.f / (float)(je - js) : 0.f;
        float4 o;
        o.x = (a0 + b0) * inv; o.y = (a1 + b1) * inv;
        o.z = (a2 + b2) * inv; o.w = (a3 + b3) * inv;
        *(float4*)(agg + (size_t)node * 128 + c) = o;
    } else {
        const int c = lid * 2;
        float a0 = 0.f, a1 = 0.f, b0 = 0.f, b1 = 0.f;
        int j = js;
        for (; j + 4 <= je; j += 4) {
            int u0 = g_col[j], u1 = g_col[j + 1], u2 = g_col[j + 2], u3 = g_col[j + 3];
            float2 v0 = *(const float2*)(h + (size_t)u0 * 64 + c);
            float2 v1 = *(const float2*)(h + (size_t)u1 * 64 + c);
            float2 v2 = *(const float2*)(h + (size_t)u2 * 64 + c);
            float2 v3 = *(const float2*)(h + (size_t)u3 * 64 + c);
            a0 += v0.x; a1 += v0.y;
            b0 += v1.x; b1 += v1.y;
            a0 += v2.x; a1 += v2.y;
            b0 += v3.x; b1 += v3.y;
        }
        for (; j < je; j++) {
            float2 v0 = *(const float2*)(h + (size_t)g_col[j] * 64 + c);
            a0 += v0.x; a1 += v0.y;
        }
        float inv = (je > js) ? 1.f / (float)(je - js) : 0.f;
        *(float2*)(agg + (size_t)node * 64 + c) =
            make_float2((a0 + b0) * inv, (a1 + b1) * inv);
    }
}

// ---------------- HMMA bf16 split-3 dual GEMM (pipelined + ldmatrix) ----------
// out[m,:] = agg @ Wl + h @ Wr + b ; activation.
// ACT: 0 none, 1 relu, 2 leaky(0.01), 3 none + fused global pool
#define SB_STR 264
#define SA_STR 136
#define SMO_BH 0
#define SMO_BL (128 * SB_STR * 2)
#define SMO_AH (2 * 128 * SB_STR * 2)
#define SMO_AL (2 * 128 * SB_STR * 2 + 128 * SA_STR * 2)
#define SM_TOT (2 * 128 * SB_STR * 2 + 2 * 128 * SA_STR * 2)  // 204800 B

__device__ __forceinline__ void mma16816(float* d, const uint32_t* a,
                                         uint32_t b0, uint32_t b1) {
    asm volatile(
        "mma.sync.aligned.m16n8k16.row.col.f32.bf16.bf16.f32 "
        "{%0,%1,%2,%3}, {%4,%5,%6,%7}, {%8,%9}, {%0,%1,%2,%3};"
        : "+f"(d[0]), "+f"(d[1]), "+f"(d[2]), "+f"(d[3])
        : "r"(a[0]), "r"(a[1]), "r"(a[2]), "r"(a[3]), "r"(b0), "r"(b1));
}

__device__ __forceinline__ void ldsm4(uint32_t* r, uint32_t addr) {
    asm volatile("ldmatrix.sync.aligned.m8n8.x4.shared.b16 {%0,%1,%2,%3}, [%4];"
                 : "=r"(r[0]), "=r"(r[1]), "=r"(r[2]), "=r"(r[3]) : "r"(addr));
}

// prefetch one A-stage (128 rows x up-to-128 cols) into registers
template <int KIN>
__device__ __forceinline__ void ld_stage(float4* R, const float* __restrict__ X,
                                         int row0, int tid) {
#pragma unroll
    for (int i = 0; i < 16; i++) {
        int it = tid + 256 * i;
        int row = it >> 5, k0 = (it & 31) * 4;
        float4 v = make_float4(0.f, 0.f, 0.f, 0.f);
        int gr = row0 + row;
        if (gr < NN && k0 < KIN)
            v = *(const float4*)(X + (size_t)gr * KIN + k0);
        R[i] = v;
    }
}

// convert + store prefetched stage into split smem
__device__ __forceinline__ void st_stage(const float4* R, __nv_bfloat16* sAh,
                                         __nv_bfloat16* sAl, int tid) {
#pragma unroll
    for (int i = 0; i < 16; i++) {
        int it = tid + 256 * i;
        int row = it >> 5, k0 = (it & 31) * 4;
        float4 v = R[i];
        float h0 = __bfloat162float(__float2bfloat16(v.x));
        float h1 = __bfloat162float(__float2bfloat16(v.y));
        float h2 = __bfloat162float(__float2bfloat16(v.z));
        float h3 = __bfloat162float(__float2bfloat16(v.w));
        *(uint2*)&sAh[row * SA_STR + k0] =
            make_uint2(packbf2(v.x, v.y), packbf2(v.z, v.w));
        *(uint2*)&sAl[row * SA_STR + k0] =
            make_uint2(packbf2(v.x - h0, v.y - h1), packbf2(v.z - h2, v.w - h3));
    }
}

// ldmatrix-based mainloop. aAh/aAl: per-thread A ldsm base (mt adds 16*SA_STR*2).
// aBh/aBl: per-thread B ldsm base (ntp adds 16*SB_STR*2). kgbase: B k offset.
template <int KSTEPS>
__device__ __forceinline__ void run_mma(float acc[2][8][4],
        uint32_t aAh, uint32_t aAl, uint32_t aBh, uint32_t aBl, int kgbase) {
#pragma unroll
    for (int ks = 0; ks < KSTEPS; ks++) {
        const int k0 = ks * 16;
        const int kg = kgbase + k0;
        uint32_t ah[2][4], al[2][4];
#pragma unroll
        for (int mt = 0; mt < 2; mt++) {
            ldsm4(ah[mt], aAh + mt * (16 * SA_STR * 2) + k0 * 2);
            ldsm4(al[mt], aAl + mt * (16 * SA_STR * 2) + k0 * 2);
        }
#pragma unroll
        for (int ntp = 0; ntp < 4; ntp++) {
            uint32_t bh[4], bl[4];
            ldsm4(bh, aBh + ntp * (16 * SB_STR * 2) + kg * 2);
            ldsm4(bl, aBl + ntp * (16 * SB_STR * 2) + kg * 2);
#pragma unroll
            for (int mt = 0; mt < 2; mt++) {
                mma16816(acc[mt][2 * ntp + 0], ah[mt], bh[0], bh[1]);
                mma16816(acc[mt][2 * ntp + 0], ah[mt], bl[0], bl[1]);
                mma16816(acc[mt][2 * ntp + 0], al[mt], bh[0], bh[1]);
                mma16816(acc[mt][2 * ntp + 1], ah[mt], bh[2], bh[3]);
                mma16816(acc[mt][2 * ntp + 1], ah[mt], bl[2], bl[3]);
                mma16816(acc[mt][2 * ntp + 1], al[mt], bh[2], bh[3]);
            }
        }
    }
}

template <int KIN, int ACT>
__global__ void __launch_bounds__(256)
k_hgemm(const float* __restrict__ Xa, const float* __restrict__ Xh,
        const int* __restrict__ batch,
        const __nv_bfloat16* __restrict__ Bhi, const __nv_bfloat16* __restrict__ Blo,
        const float* __restrict__ bias, float* __restrict__ out) {
    extern __shared__ char sm[];
    __nv_bfloat16* sBh = (__nv_bfloat16*)(sm + SMO_BH);
    __nv_bfloat16* sBl = (__nv_bfloat16*)(sm + SMO_BL);
    __nv_bfloat16* sAh = (__nv_bfloat16*)(sm + SMO_AH);
    __nv_bfloat16* sAl = (__nv_bfloat16*)(sm + SMO_AL);

    const int tid = threadIdx.x;
    const int wid = tid >> 5, lid = tid & 31;
    const int g = lid >> 2, tig = lid & 3;
    const int m0 = (wid & 3) * 32;
    const int n0 = (wid >> 2) * 64;

    for (int i = tid; i < 4096; i += 256) {
        int n = i >> 5, kq = i & 31;
        float4 vh = ((const float4*)Bhi)[i];
        float4 vl = ((const float4*)Blo)[i];
        *(float4*)&sBh[n * SB_STR + kq * 8] = vh;
        *(float4*)&sBl[n * SB_STR + kq * 8] = vl;
    }

    // per-thread ldmatrix base addresses
    const uint32_t sAh32 = (uint32_t)__cvta_generic_to_shared(sAh);
    const uint32_t sAl32 = (uint32_t)__cvta_generic_to_shared(sAl);
    const uint32_t sBh32 = (uint32_t)__cvta_generic_to_shared(sBh);
    const uint32_t sBl32 = (uint32_t)__cvta_generic_to_shared(sBl);
    const int arow = m0 + (lid & 15);
    const int akex = (lid >> 4) * 8;
    const uint32_t aAh = sAh32 + (uint32_t)(arow * SA_STR + akex) * 2;
    const uint32_t aAl = sAl32 + (uint32_t)(arow * SA_STR + akex) * 2;
    const int brow = n0 + ((lid >> 4) & 1) * 8 + (lid & 7);
    const int bkex = ((lid >> 3) & 1) * 8;
    const uint32_t aBh = sBh32 + (uint32_t)(brow * SB_STR + bkex) * 2;
    const uint32_t aBl = sBl32 + (uint32_t)(brow * SB_STR + bkex) * 2;

    constexpr int KSTEPS = (KIN == 64) ? 4 : 8;

    float4 R[16];
    ld_stage<KIN>(R, Xa, blockIdx.x * 128, tid);   // prefetch first tile, stage 0

    for (int t = blockIdx.x; t < NTILES; t += GRID_G) {
        const int row0 = t * 128;
        float acc[2][8][4];
#pragma unroll
        for (int mt = 0; mt < 2; mt++)
#pragma unroll
            for (int nt = 0; nt < 8; nt++)
#pragma unroll
                for (int q = 0; q < 4; q++) acc[mt][nt][q] = 0.f;

        // ---- stage 0 (agg term) ----
        __syncthreads();                    // prior MMA/frag reads done
        st_stage(R, sAh, sAl, tid);
        __syncthreads();
        ld_stage<KIN>(R, Xh, row0, tid);    // prefetch stage 1 (hidden by MMA)
        run_mma<KSTEPS>(acc, aAh, aAl, aBh, aBl, 0);

        // ---- stage 1 (self term) ----
        __syncthreads();
        st_stage(R, sAh, sAl, tid);
        __syncthreads();
        if (t + GRID_G < NTILES)
            ld_stage<KIN>(R, Xa, (t + GRID_G) * 128, tid);  // prefetch next tile s0
        run_mma<KSTEPS>(acc, aAh, aAl, aBh, aBl, 128);

        // ---- epilogue: bias + activation + store (or fused pool) ----
#pragma unroll
        for (int mt = 0; mt < 2; mt++) {
#pragma unroll
            for (int half = 0; half < 2; half++) {
                int gr = row0 + m0 + mt * 16 + g + half * 8;
                if (gr < NN) {
                    int bidx = (ACT == 3) ? __ldg(batch + gr) : 0;
#pragma unroll
                    for (int nt = 0; nt < 8; nt++) {
                        int c = n0 + nt * 8 + tig * 2;
                        float v0 = acc[mt][nt][half * 2 + 0] + __ldg(bias + c);
                        float v1 = acc[mt][nt][half * 2 + 1] + __ldg(bias + c + 1);
                        if (ACT == 1) {
                            v0 = fmaxf(v0, 0.f); v1 = fmaxf(v1, 0.f);
                        } else if (ACT == 2) {
                            v0 = (v0 > 0.f) ? v0 : 0.01f * v0;
                            v1 = (v1 > 0.f) ? v1 : 0.01f * v1;
                        }
                        if (ACT == 3) {
                            atomicAdd(&g_gsum[bidx * CH + c], v0);
                            atomicAdd(&g_gsum[bidx * CH + c + 1], v1);
                        } else {
                            *(float2*)(out + (size_t)gr * CH + c) = make_float2(v0, v1);
                        }
                    }
                }
            }
        }
    }
}

// ---------------- head --------------------------------------------------------
__global__ void k_head(const float* __restrict__ headW,
                       const float* __restrict__ headb,
                       float* __restrict__ out) {
    int tid = blockIdx.x * blockDim.x + threadIdx.x;
    if (tid >= GG * COUT) return;
    int g = tid >> 1;
    int o = tid & 1;
    float cnt = (float)g_gcnt[g];
    float inv = 1.f / fmaxf(cnt, 1.f);
    float acc = headb[o];
#pragma unroll 8
    for (int k = 0; k < CH; k++)
        acc += g_gsum[g * CH + k] * inv * headW[k * COUT + o];
    out[tid] = acc;
}

// ---------------- host driver -------------------------------------------------
extern "C" void kernel_launch(void* const* d_in, const int* in_sizes, int n_in,
                              void* d_out, int out_size) {
    const float* x     = (const float*)d_in[0];
    const int*   ei    = (const int*)d_in[1];
    const int*   srcp  = ei;
    const int*   dstp  = ei + EE;
    const int*   batch = (const int*)d_in[2];
    const float* Wl0   = (const float*)d_in[3];
    const float* Wr0   = (const float*)d_in[4];
    const float* b0    = (const float*)d_in[5];
    const float* Wl    = (const float*)d_in[6];
    const float* Wr    = (const float*)d_in[7];
    const float* bb    = (const float*)d_in[8];
    const float* headW = (const float*)d_in[9];
    const float* headb = (const float*)d_in[10];
    float* out = (float*)d_out;

    float *hA, *hB, *agg;
    __nv_bfloat16 *Bhi, *Blo;
    cudaGetSymbolAddress((void**)&hA, g_hA);
    cudaGetSymbolAddress((void**)&hB, g_hB);
    cudaGetSymbolAddress((void**)&agg, g_agg);
    cudaGetSymbolAddress((void**)&Bhi, g_Bhi);
    cudaGetSymbolAddress((void**)&Blo, g_Blo);

    cudaFuncSetAttribute(k_hgemm<64, 1>,  cudaFuncAttributeMaxDynamicSharedMemorySize, SM_TOT);
    cudaFuncSetAttribute(k_hgemm<128, 1>, cudaFuncAttributeMaxDynamicSharedMemorySize, SM_TOT);
    cudaFuncSetAttribute(k_hgemm<128, 2>, cudaFuncAttributeMaxDynamicSharedMemorySize, SM_TOT);
    cudaFuncSetAttribute(k_hgemm<128, 3>, cudaFuncAttributeMaxDynamicSharedMemorySize, SM_TOT);

    // --- preprocessing: grid-parallel, 6 launches ---
    k_init_prepw<<<(12 * 32768 + 255) / 256, 256>>>(Wl0, Wr0, Wl, Wr);
    k_count2<<<(EE + 255) / 256, 256>>>(dstp, batch);
    k_scan1<<<(NN + 1023) / 1024, 1024>>>();
    k_scan2<<<1, 32>>>((NN + 1023) / 1024);
    k_scan3<<<(NN + 255) / 256, 256>>>();
    k_fill<<<(EE + 255) / 256, 256>>>(srcp, dstp);

    // --- conv 0: C_IN=64 -> 128, ReLU ---
    k_agg<64><<<(NN + 7) / 8, 256>>>(x, agg);
    k_hgemm<64, 1><<<GRID_G, 256, SM_TOT>>>(agg, x, batch, Bhi, Blo, b0, hA);

    // --- convs 1..11 (conv 11 fuses global mean pool) ---
    const int act[11] = {1, 1, 2, 1, 1, 1, 2, 1, 1, 1, 3};
    const float* cur = hA;
    float* nxt = hB;
    for (int li = 0; li < 11; li++) {
        k_agg<128><<<(NN + 7) / 8, 256>>>(cur, agg);
        const __nv_bfloat16* bh = Bhi + (size_t)(li + 1) * 32768;
        const __nv_bfloat16* bl = Blo + (size_t)(li + 1) * 32768;
        const float* bi = bb + (size_t)li * CH;
        if (act[li] == 1)
            k_hgemm<128, 1><<<GRID_G, 256, SM_TOT>>>(agg, cur, batch, bh, bl, bi, nxt);
        else if (act[li] == 2)
            k_hgemm<128, 2><<<GRID_G, 256, SM_TOT>>>(agg, cur, batch, bh, bl, bi, nxt);
        else
            k_hgemm<128, 3><<<GRID_G, 256, SM_TOT>>>(agg, cur, batch, bh, bl, bi, nxt);
        const float* t = cur;
        cur = nxt;
        nxt = (float*)t;
    }

    // --- head ---
    k_head<<<(GG * COUT + 255) / 256, 256>>>(headW, headb, out);
}